// round 2
// baseline (speedup 1.0000x reference)
#include <cuda_runtime.h>
#include <math.h>

#define BB 4
#define SS 1024
#define DD 256
#define HH 512
#define NTY 20
#define NSMP 50
#define MM (BB*SS)          /* 4096 (b,s) rows */
#define RTOT (MM*NSMP)      /* 204800 GEMM rows */

typedef unsigned long long ull;

/* ---------------- scratch (device globals; no allocs allowed) -------------- */
__device__ __align__(16) float g_hvec[MM*HH];   /* [b,s, pe|temb]   8MB */
__device__ __align__(16) float g_hid [MM*HH];   /* aggregated / post-LN 8MB */
__device__ __align__(16) float g_y   [MM*HH];   /* hln @ w_in^T     8MB */
__device__ __align__(16) float g_wnT [HH*HH];   /* w_noise^T (k-major) 1MB */
__device__ float g_asv[MM], g_bsv[MM], g_agv[MM], g_bgv[MM];

/* ---------------- small helpers ---------------- */
__device__ __forceinline__ ull ffma2(ull a, ull b, ull c){
  ull d; asm("fma.rn.f32x2 %0, %1, %2, %3;" : "=l"(d) : "l"(a), "l"(b), "l"(c)); return d;
}
union F2 { ull u; float2 f; };
__device__ __forceinline__ ull pack2(float x, float y){ F2 t; t.f = make_float2(x,y); return t.u; }

__device__ __forceinline__ float block_sum256(float v){
  __shared__ float sh[8];
  int lane = threadIdx.x & 31, w = threadIdx.x >> 5;
  #pragma unroll
  for(int o=16;o;o>>=1) v += __shfl_xor_sync(0xffffffffu, v, o);
  if(lane==0) sh[w] = v;
  __syncthreads();
  if(w==0){
    float r = (lane<8)?sh[lane]:0.f;
    #pragma unroll
    for(int o=4;o;o>>=1) r += __shfl_xor_sync(0xffffffffu, r, o);
    if(lane==0) sh[0]=r;
  }
  __syncthreads();
  float r = sh[0];
  __syncthreads();
  return r;
}

__device__ __forceinline__ float softplusf(float x){
  return fmaxf(x,0.f) + log1pf(expf(-fabsf(x)));
}

/* -------- k0: transpose w_noise into k-major (coalesced tile loads later) -- */
__global__ void k0_tr(const float* __restrict__ wn){
  int k = blockIdx.x, j = threadIdx.x;
  g_wnT[(size_t)k*HH + j] = wn[(size_t)j*HH + k];
}

/* -------- k1: pe + type emb + per-event sigma/gate projections ------------- */
__global__ void k1_pre(const int* __restrict__ etype, const float* __restrict__ etime,
                       const float* __restrict__ wt, const float* __restrict__ table,
                       const float* __restrict__ wsig, const float* __restrict__ wgate){
  int bs = blockIdx.x; int t = threadIdx.x;
  int s = bs & (SS-1);
  float tv = table[(size_t)etype[bs]*DD + t];
  float tm = etime[bs];
  if(t < DD/2){
    double div = exp(-(double)(2*t) * (9.210340371976184/256.0)); /* ln(1e4)/d */
    float arg = (float)((double)s * div) + tm * wt[t];
    g_hvec[(size_t)bs*HH + t]        = sinf(arg);
    g_hvec[(size_t)bs*HH + DD/2 + t] = cosf(arg);
  }
  g_hvec[(size_t)bs*HH + DD + t] = tv;
  float r;
  r = block_sum256(tv * wsig[t]);      if(t==0) g_asv[bs]=r;
  r = block_sum256(tv * wsig[DD+t]);   if(t==0) g_bsv[bs]=r;
  r = block_sum256(tv * wgate[t]);     if(t==0) g_agv[bs]=r;
  r = block_sum256(tv * wgate[DD+t]);  if(t==0) g_bgv[bs]=r;
}

/* -------- k2: causal gated score aggregation, TI=8 rows per block ---------- */
__global__ void k2_agg(const float* __restrict__ etime){
  __shared__ ull s_w[8][256];
  __shared__ float s_bs[8], s_bg[8], s_ti[8];
  int bx = blockIdx.x; int b = bx >> 7; int i0 = (bx & 127) << 3;
  int t = threadIdx.x;
  if(t < 8){
    int i = b*SS + i0 + t;
    s_bs[t] = g_bsv[i]; s_bg[t] = g_bgv[i]; s_ti[t] = etime[i];
  }
  __syncthreads();
  ull acc[8];
  #pragma unroll
  for(int r=0;r<8;r++) acc[r]=0ull;
  int jend = i0 + 7;                 /* max needed j is i0+6 (strict causal) */
  for(int j0=0;j0<jend;j0+=256){
    int j = j0 + t;
    float aj_s = g_asv[b*SS+j], aj_g = g_agv[b*SS+j], tj = etime[b*SS+j];
    #pragma unroll
    for(int r=0;r<8;r++){
      float xs   = aj_s + s_bs[r];
      float sig  = softplusf(xs);
      float xg   = aj_g + s_bg[r];
      float gate = 1.f/(1.f+expf(-xg));
      float td   = fabsf(s_ti[r]-tj);
      float wv   = (j < i0+r) ? gate*expf(-sig*td) : 0.f;
      s_w[r][t]  = pack2(wv, wv);
    }
    __syncthreads();
    int jcnt = min(256, jend - j0);
    const ull* hv = reinterpret_cast<const ull*>(g_hvec) + ((size_t)(b*SS + j0))*256 + t;
    #pragma unroll 2
    for(int jj=0;jj<jcnt;jj++){
      ull v = hv[(size_t)jj*256];
      #pragma unroll
      for(int r=0;r<8;r++) acc[r] = ffma2(s_w[r][jj], v, acc[r]);
    }
    __syncthreads();
  }
  #pragma unroll
  for(int r=0;r<8;r++)
    reinterpret_cast<ull*>(g_hid)[((size_t)(b*SS + i0 + r))*256 + t] = acc[r];
}

/* -------- k3: LayerNorm (in-place) + mark_probs softmax -------------------- */
__global__ void k3_ln(const float* __restrict__ gamma, const float* __restrict__ beta,
                      const float* __restrict__ wpred, float* __restrict__ marks){
  __shared__ float s_n[HH];
  __shared__ float slog[NTY];
  int bs = blockIdx.x, t = threadIdx.x;
  float2 h = reinterpret_cast<const float2*>(g_hid)[(size_t)bs*256 + t];
  float mean = block_sum256(h.x + h.y) * (1.f/HH);
  float dx = h.x - mean, dy = h.y - mean;
  float var = block_sum256(dx*dx + dy*dy) * (1.f/HH);
  float inv = rsqrtf(var + 1e-6f);
  float n0 = dx*inv*gamma[2*t]   + beta[2*t];
  float n1 = dy*inv*gamma[2*t+1] + beta[2*t+1];
  reinterpret_cast<float2*>(g_hid)[(size_t)bs*256 + t] = make_float2(n0,n1);
  s_n[2*t]=n0; s_n[2*t+1]=n1;
  __syncthreads();
  int lane = t & 31, w = t >> 5;
  for(int nt = w; nt < NTY; nt += 8){
    float p = 0.f;
    for(int k=lane;k<HH;k+=32) p += s_n[k]*wpred[(size_t)nt*HH+k];
    #pragma unroll
    for(int o=16;o;o>>=1) p += __shfl_xor_sync(0xffffffffu,p,o);
    if(lane==0) slog[nt]=p;
  }
  __syncthreads();
  if(t==0){
    float mx=-1e30f;
    for(int c=0;c<NTY;c++) mx = fmaxf(mx, slog[c]);
    float e[NTY], sum=0.f;
    for(int c=0;c<NTY;c++){ e[c]=expf(slog[c]-mx); sum+=e[c]; }
    float is = 1.f/sum;
    for(int c=0;c<NTY;c++) marks[(size_t)bs*NTY + c] = e[c]*is;
  }
}

/* -------- k3b: y = hln @ w_in^T  (tiled 64x64 GEMM, M=4096,N=512,K=512) ---- */
__global__ void k3_y(const float* __restrict__ w_in){
  __shared__ float As[64][33];
  __shared__ float Bs[64][33];
  int m0 = blockIdx.x*64, j0 = blockIdx.y*64;
  int t = threadIdx.x;
  int tx = t & 15, ty = t >> 4;
  float acc[4][4] = {};
  for(int k0=0;k0<HH;k0+=32){
    #pragma unroll
    for(int i=0;i<8;i++){
      int l = t + i*256;
      int r = l>>5, kk = l&31;
      As[r][kk] = g_hid[((size_t)(m0+r))*HH + k0+kk];
      Bs[r][kk] = w_in [((size_t)(j0+r))*HH + k0+kk];
    }
    __syncthreads();
    #pragma unroll 8
    for(int kk=0;kk<32;kk++){
      float a[4], bb[4];
      #pragma unroll
      for(int i=0;i<4;i++) a[i]=As[ty*4+i][kk];
      #pragma unroll
      for(int j=0;j<4;j++) bb[j]=Bs[tx*4+j][kk];
      #pragma unroll
      for(int i=0;i<4;i++){
        #pragma unroll
        for(int j=0;j<4;j++) acc[i][j] = fmaf(a[i],bb[j],acc[i][j]);
      }
    }
    __syncthreads();
  }
  #pragma unroll
  for(int i=0;i<4;i++){
    float4 v = make_float4(acc[i][0],acc[i][1],acc[i][2],acc[i][3]);
    *reinterpret_cast<float4*>(&g_y[((size_t)(m0+ty*4+i))*HH + j0 + tx*4]) = v;
  }
}

/* -------- k4: fused big GEMM  relu(noise@Wn^T + y) . w_time -> softplus/mean
   64 rows x 512 cols per block; noise tile fully SMEM-resident (read once
   from DRAM); W tiles double-buffered from L2; epilogue never materializes z. */
__global__ __launch_bounds__(256) void k4_gemm(const float* __restrict__ noise,
                                               const float* __restrict__ wtime,
                                               float* __restrict__ pred){
  extern __shared__ float smem[];
  float* As = smem;              /* 64*512 = 128KB */
  float* Ws = smem + 64*512;     /* 2*32*128 = 32KB (double buffer) */
  int t = threadIdx.x;
  int tx = t & 31, ty = t >> 5;
  int m0 = blockIdx.x * 64;

  { /* stage full A tile (coalesced float4) */
    const float4* src = reinterpret_cast<const float4*>(noise + (size_t)m0*HH);
    float4* dst = reinterpret_cast<float4*>(As);
    #pragma unroll
    for(int i=0;i<32;i++) dst[t + i*256] = src[t + i*256];
  }
  float4 pre[4];
  { /* prefetch W tile p=0 */
    #pragma unroll
    for(int i=0;i<4;i++){ int l = t + i*256;
      pre[i] = *reinterpret_cast<const float4*>(g_wnT + (size_t)(l>>5)*HH + (l&31)*4); }
  }
  float rsum[8];
  #pragma unroll
  for(int r=0;r<8;r++) rsum[r]=0.f;

  int p = 0;
  for(int jt=0;jt<4;jt++){
    ull acc[8][2];
    #pragma unroll
    for(int r=0;r<8;r++){ acc[r][0]=0ull; acc[r][1]=0ull; }
    for(int kt=0;kt<16;kt++,p++){
      __syncthreads();
      { /* commit prefetched tile to smem */
        float4* wdst = reinterpret_cast<float4*>(Ws + (p&1)*4096);
        #pragma unroll
        for(int i=0;i<4;i++) wdst[t + i*256] = pre[i];
      }
      if(p+1 < 64){ /* prefetch next tile */
        int pn = p+1; int jt2 = pn>>4, kt2 = pn&15;
        const float* base = g_wnT + (size_t)(kt2*32)*HH + jt2*128;
        #pragma unroll
        for(int i=0;i<4;i++){ int l = t + i*256;
          pre[i] = *reinterpret_cast<const float4*>(base + (size_t)(l>>5)*HH + (l&31)*4); }
      }
      __syncthreads();
      const float* wbase = Ws + (p&1)*4096 + tx*4;
      const float* abase = As + kt*32 + ty*8*HH;
      #pragma unroll 8
      for(int kk=0;kk<32;kk++){
        ull w0 = *reinterpret_cast<const ull*>(wbase + kk*128);
        ull w1 = *reinterpret_cast<const ull*>(wbase + kk*128 + 2);
        #pragma unroll
        for(int r=0;r<8;r++){
          float a = abase[r*HH + kk];
          ull ap = pack2(a,a);
          acc[r][0] = ffma2(ap, w0, acc[r][0]);
          acc[r][1] = ffma2(ap, w1, acc[r][1]);
        }
      }
    }
    /* epilogue for this 128-col slab: bias + relu + w_time partial dot */
    float4 wt4 = *reinterpret_cast<const float4*>(wtime + jt*128 + tx*4);
    #pragma unroll
    for(int r=0;r<8;r++){
      int m = m0 + ty*8 + r;
      int bsid = m / NSMP;
      float4 yv = *reinterpret_cast<const float4*>(&g_y[(size_t)bsid*HH + jt*128 + tx*4]);
      F2 u0; u0.u = acc[r][0];
      F2 u1; u1.u = acc[r][1];
      float z0 = u0.f.x + yv.x, z1 = u0.f.y + yv.y;
      float z2 = u1.f.x + yv.z, z3 = u1.f.y + yv.w;
      rsum[r] += fmaxf(z0,0.f)*wt4.x + fmaxf(z1,0.f)*wt4.y
               + fmaxf(z2,0.f)*wt4.z + fmaxf(z3,0.f)*wt4.w;
    }
  }
  /* per-row reduce across the 32 col-lanes, softplus, mean over NS */
  #pragma unroll
  for(int r=0;r<8;r++){
    float v = rsum[r];
    #pragma unroll
    for(int o=16;o;o>>=1) v += __shfl_xor_sync(0xffffffffu, v, o);
    if(tx==0){
      int m = m0 + ty*8 + r;
      int bsid = m / NSMP;
      atomicAdd(pred + bsid, softplusf(v) * (1.f/NSMP));
    }
  }
}

/* ---------------- launch ---------------- */
extern "C" void kernel_launch(void* const* d_in, const int* in_sizes, int n_in,
                              void* d_out, int out_size){
  const int*   etype  = (const int*)  d_in[0];
  const float* etime  = (const float*)d_in[1];
  const float* noise  = (const float*)d_in[2];
  const float* wt     = (const float*)d_in[3];
  const float* table  = (const float*)d_in[4];
  const float* wsig   = (const float*)d_in[5];
  const float* wgate  = (const float*)d_in[6];
  const float* gamma  = (const float*)d_in[7];
  const float* beta   = (const float*)d_in[8];
  const float* wpred  = (const float*)d_in[9];
  const float* w_in   = (const float*)d_in[10];
  const float* wnoise = (const float*)d_in[11];
  const float* wtime  = (const float*)d_in[12];
  float* out = (float*)d_out;

  const int k4_smem = 64*512*4 + 2*32*128*4; /* 160KB */
  cudaFuncSetAttribute(k4_gemm, cudaFuncAttributeMaxDynamicSharedMemorySize, k4_smem);

  cudaMemsetAsync(out, 0, MM*sizeof(float));          /* pred accum region */
  k0_tr <<<HH, HH>>>(wnoise);
  k1_pre<<<MM, 256>>>(etype, etime, wt, table, wsig, wgate);
  k2_agg<<<BB*(SS/8), 256>>>(etime);
  k3_ln <<<MM, 256>>>(gamma, beta, wpred, out + MM);
  k3_y  <<<dim3(MM/64, HH/64), 256>>>(w_in);
  k4_gemm<<<RTOT/64, 256, k4_smem>>>(noise, wtime, out);
}

// round 5
// speedup vs baseline: 2.2748x; 2.2748x over previous
#include <cuda_runtime.h>
#include <cuda_bf16.h>
#include <math.h>
#include <stdint.h>

#define BB 4
#define SS 1024
#define DD 256
#define HH 512
#define NTY 20
#define NSMP 50
#define MM (BB*SS)          /* 4096 (b,s) rows */
#define RTOT (MM*NSMP)      /* 204800 GEMM rows */

typedef unsigned long long ull;
typedef unsigned int uint32;

/* ---------------- scratch (device globals; no allocs allowed) -------------- */
__device__ __align__(16) float g_hvec[MM*HH];   /* [b,s, pe|temb]   8MB */
__device__ __align__(16) float g_hid [MM*HH];   /* aggregated / post-LN 8MB */
__device__ __align__(16) float g_y   [MM*HH];   /* hln @ w_in^T     8MB */
/* w_noise split bf16, k-chunk-major: elem (n,k) at (k/16)*8192 + n*16 + (k%16) */
__device__ __align__(16) __nv_bfloat16 g_wbh[HH*HH];
__device__ __align__(16) __nv_bfloat16 g_wbl[HH*HH];
__device__ float g_asv[MM], g_bsv[MM], g_agv[MM], g_bgv[MM];

/* ---------------- small helpers ---------------- */
__device__ __forceinline__ ull ffma2(ull a, ull b, ull c){
  ull d; asm("fma.rn.f32x2 %0, %1, %2, %3;" : "=l"(d) : "l"(a), "l"(b), "l"(c)); return d;
}
union F2 { ull u; float2 f; };
__device__ __forceinline__ ull pack2(float x, float y){ F2 t; t.f = make_float2(x,y); return t.u; }

__device__ __forceinline__ float block_sum256(float v){
  __shared__ float sh[8];
  int lane = threadIdx.x & 31, w = threadIdx.x >> 5;
  #pragma unroll
  for(int o=16;o;o>>=1) v += __shfl_xor_sync(0xffffffffu, v, o);
  if(lane==0) sh[w] = v;
  __syncthreads();
  if(w==0){
    float r = (lane<8)?sh[lane]:0.f;
    #pragma unroll
    for(int o=4;o;o>>=1) r += __shfl_xor_sync(0xffffffffu, r, o);
    if(lane==0) sh[0]=r;
  }
  __syncthreads();
  float r = sh[0];
  __syncthreads();
  return r;
}

__device__ __forceinline__ float softplusf(float x){
  return fmaxf(x,0.f) + log1pf(expf(-fabsf(x)));
}

__device__ __forceinline__ uint32 smem_u32(const void* p){
  uint32 a; asm("{ .reg .u64 t; cvta.to.shared.u64 t, %1; cvt.u32.u64 %0, t; }" : "=r"(a) : "l"(p));
  return a;
}

/* ---------------- sm80-class tensor core primitives (portable) ------------- */
#define LDSM4(rg, addr) \
  asm volatile("ldmatrix.sync.aligned.m8n8.x4.shared.b16 {%0,%1,%2,%3}, [%4];" \
    : "=r"((rg)[0]),"=r"((rg)[1]),"=r"((rg)[2]),"=r"((rg)[3]) : "r"(addr))

#define MMA16816(cd, a, b0, b1) \
  asm volatile("mma.sync.aligned.m16n8k16.row.col.f32.bf16.bf16.f32 " \
    "{%0,%1,%2,%3},{%4,%5,%6,%7},{%8,%9},{%0,%1,%2,%3};" \
    : "+f"((cd)[0]),"+f"((cd)[1]),"+f"((cd)[2]),"+f"((cd)[3]) \
    : "r"((a)[0]),"r"((a)[1]),"r"((a)[2]),"r"((a)[3]), "r"(b0),"r"(b1))

#define CPA16(s,g)  asm volatile("cp.async.cg.shared.global [%0], [%1], 16;" :: "r"(s), "l"(g))
#define CPCOMMIT()  asm volatile("cp.async.commit_group;" ::: "memory")
#define CPWAIT(n)   asm volatile("cp.async.wait_group %0;" :: "n"(n) : "memory")

/* -------- k0: split w_noise into bf16 hi/lo, k-chunk-major ----------------- */
__global__ void k0_convB(const float* __restrict__ wn){
  int g = blockIdx.x*256 + threadIdx.x;       /* 32768 threads, 8 elems each */
  int n = g >> 6; int k = (g & 63) * 8;
  const float4* s = reinterpret_cast<const float4*>(wn + (size_t)n*HH + k);
  float4 v0 = s[0], v1 = s[1];
  float xs[8] = {v0.x,v0.y,v0.z,v0.w,v1.x,v1.y,v1.z,v1.w};
  union { __nv_bfloat16 b[8]; uint4 u; } hi, lo;
  #pragma unroll
  for(int e=0;e<8;e++){
    __nv_bfloat16 h = __float2bfloat16_rn(xs[e]);
    hi.b[e] = h;
    lo.b[e] = __float2bfloat16_rn(xs[e] - __bfloat162float(h));
  }
  int dst = (k>>4)*8192 + n*16 + (k&15);
  *reinterpret_cast<uint4*>(g_wbh + dst) = hi.u;
  *reinterpret_cast<uint4*>(g_wbl + dst) = lo.u;
}

/* -------- k1: pe + type emb + per-event sigma/gate projections ------------- */
__global__ void k1_pre(const int* __restrict__ etype, const float* __restrict__ etime,
                       const float* __restrict__ wt, const float* __restrict__ table,
                       const float* __restrict__ wsig, const float* __restrict__ wgate){
  int bs = blockIdx.x; int t = threadIdx.x;
  int s = bs & (SS-1);
  float tv = table[(size_t)etype[bs]*DD + t];
  float tm = etime[bs];
  if(t < DD/2){
    double div = exp(-(double)(2*t) * (9.210340371976184/256.0)); /* ln(1e4)/d */
    float arg = (float)((double)s * div) + tm * wt[t];
    g_hvec[(size_t)bs*HH + t]        = sinf(arg);
    g_hvec[(size_t)bs*HH + DD/2 + t] = cosf(arg);
  }
  g_hvec[(size_t)bs*HH + DD + t] = tv;
  float r;
  r = block_sum256(tv * wsig[t]);      if(t==0) g_asv[bs]=r;
  r = block_sum256(tv * wsig[DD+t]);   if(t==0) g_bsv[bs]=r;
  r = block_sum256(tv * wgate[t]);     if(t==0) g_agv[bs]=r;
  r = block_sum256(tv * wgate[DD+t]);  if(t==0) g_bgv[bs]=r;
}

/* -------- k2: causal gated score aggregation, TI=8 rows per block ---------- */
__global__ void k2_agg(const float* __restrict__ etime){
  __shared__ ull s_w[8][256];
  __shared__ float s_bs[8], s_bg[8], s_ti[8];
  int bx = blockIdx.x; int b = bx >> 7; int i0 = (bx & 127) << 3;
  int t = threadIdx.x;
  if(t < 8){
    int i = b*SS + i0 + t;
    s_bs[t] = g_bsv[i]; s_bg[t] = g_bgv[i]; s_ti[t] = etime[i];
  }
  __syncthreads();
  ull acc[8];
  #pragma unroll
  for(int r=0;r<8;r++) acc[r]=0ull;
  int jend = i0 + 7;
  for(int j0=0;j0<jend;j0+=256){
    int j = j0 + t;
    float aj_s = g_asv[b*SS+j], aj_g = g_agv[b*SS+j], tj = etime[b*SS+j];
    #pragma unroll
    for(int r=0;r<8;r++){
      float xs   = aj_s + s_bs[r];
      float sig  = softplusf(xs);
      float xg   = aj_g + s_bg[r];
      float gate = 1.f/(1.f+expf(-xg));
      float td   = fabsf(s_ti[r]-tj);
      float wv   = (j < i0+r) ? gate*expf(-sig*td) : 0.f;
      s_w[r][t]  = pack2(wv, wv);
    }
    __syncthreads();
    int jcnt = min(256, jend - j0);
    const ull* hv = reinterpret_cast<const ull*>(g_hvec) + ((size_t)(b*SS + j0))*256 + t;
    #pragma unroll 2
    for(int jj=0;jj<jcnt;jj++){
      ull v = hv[(size_t)jj*256];
      #pragma unroll
      for(int r=0;r<8;r++) acc[r] = ffma2(s_w[r][jj], v, acc[r]);
    }
    __syncthreads();
  }
  #pragma unroll
  for(int r=0;r<8;r++)
    reinterpret_cast<ull*>(g_hid)[((size_t)(b*SS + i0 + r))*256 + t] = acc[r];
}

/* -------- k3: LayerNorm (in-place) + mark_probs softmax -------------------- */
__global__ void k3_ln(const float* __restrict__ gamma, const float* __restrict__ beta,
                      const float* __restrict__ wpred, float* __restrict__ marks){
  __shared__ float s_n[HH];
  __shared__ float slog[NTY];
  int bs = blockIdx.x, t = threadIdx.x;
  float2 h = reinterpret_cast<const float2*>(g_hid)[(size_t)bs*256 + t];
  float mean = block_sum256(h.x + h.y) * (1.f/HH);
  float dx = h.x - mean, dy = h.y - mean;
  float var = block_sum256(dx*dx + dy*dy) * (1.f/HH);
  float inv = rsqrtf(var + 1e-6f);
  float n0 = dx*inv*gamma[2*t]   + beta[2*t];
  float n1 = dy*inv*gamma[2*t+1] + beta[2*t+1];
  reinterpret_cast<float2*>(g_hid)[(size_t)bs*256 + t] = make_float2(n0,n1);
  s_n[2*t]=n0; s_n[2*t+1]=n1;
  __syncthreads();
  int lane = t & 31, w = t >> 5;
  for(int nt = w; nt < NTY; nt += 8){
    float p = 0.f;
    for(int k=lane;k<HH;k+=32) p += s_n[k]*wpred[(size_t)nt*HH+k];
    #pragma unroll
    for(int o=16;o;o>>=1) p += __shfl_xor_sync(0xffffffffu,p,o);
    if(lane==0) slog[nt]=p;
  }
  __syncthreads();
  if(t==0){
    float mx=-1e30f;
    for(int c=0;c<NTY;c++) mx = fmaxf(mx, slog[c]);
    float e[NTY], sum=0.f;
    for(int c=0;c<NTY;c++){ e[c]=expf(slog[c]-mx); sum+=e[c]; }
    float is = 1.f/sum;
    for(int c=0;c<NTY;c++) marks[(size_t)bs*NTY + c] = e[c]*is;
  }
}

/* -------- k3b: y = hln @ w_in^T  (tiled 64x64 GEMM, M=4096,N=512,K=512) ---- */
__global__ void k3_y(const float* __restrict__ w_in){
  __shared__ float As[64][33];
  __shared__ float Bs[64][33];
  int m0 = blockIdx.x*64, j0 = blockIdx.y*64;
  int t = threadIdx.x;
  int tx = t & 15, ty = t >> 4;
  float acc[4][4] = {};
  for(int k0=0;k0<HH;k0+=32){
    #pragma unroll
    for(int i=0;i<8;i++){
      int l = t + i*256;
      int r = l>>5, kk = l&31;
      As[r][kk] = g_hid[((size_t)(m0+r))*HH + k0+kk];
      Bs[r][kk] = w_in [((size_t)(j0+r))*HH + k0+kk];
    }
    __syncthreads();
    #pragma unroll 8
    for(int kk=0;kk<32;kk++){
      float a[4], bb[4];
      #pragma unroll
      for(int i=0;i<4;i++) a[i]=As[ty*4+i][kk];
      #pragma unroll
      for(int j=0;j<4;j++) bb[j]=Bs[tx*4+j][kk];
      #pragma unroll
      for(int i=0;i<4;i++){
        #pragma unroll
        for(int j=0;j<4;j++) acc[i][j] = fmaf(a[i],bb[j],acc[i][j]);
      }
    }
    __syncthreads();
  }
  #pragma unroll
  for(int i=0;i<4;i++){
    float4 v = make_float4(acc[i][0],acc[i][1],acc[i][2],acc[i][3]);
    *reinterpret_cast<float4*>(&g_y[((size_t)(m0+ty*4+i))*HH + j0 + tx*4]) = v;
  }
}

/* -------- k4: split-bf16 mma.sync GEMM + fused epilogue --------------------
   CTA tile M=64 x N=512 (full N => softplus stays fused), K=512.
   A: fp32 noise loaded once, split to bf16 hi/lo in regs, SMEM-resident (pad
   16B/row => conflict-free ldmatrix). B: k-chunk-major hi/lo tables streamed
   via cp.async (double buffer, XOR swizzle). 3 passes AhBh + AlBh + AhBl.   */
#define A_ROWB 1040                      /* (512+8)*2 bytes per A row */
#define SM_ALO  (64*A_ROWB)              /* 66560 */
#define SM_B    (2*64*A_ROWB)            /* 133120 */
#define B_CHUNK 16384                    /* 512n x 16k bf16 */
#define SM_BUF(buf,hl) (SM_B + (buf)*2*B_CHUNK + (hl)*B_CHUNK)
#define K4_SMEM (SM_B + 4*B_CHUNK)       /* 198656 */

__global__ void __launch_bounds__(256,1)
k4_mma(const float* __restrict__ noise, const float* __restrict__ wtime,
       float* __restrict__ pred){
  extern __shared__ char sm[];
  const uint32 sb = smem_u32(sm);
  const int t = threadIdx.x;
  const int lane = t & 31, w = t >> 5;
  const int wm = w & 1, wn = w >> 1;
  const size_t m0 = (size_t)blockIdx.x * 64;

  /* ---- stage A: 64 x 512 fp32 -> bf16 hi/lo in SMEM ---- */
  {
    const float4* src = reinterpret_cast<const float4*>(noise + m0*HH);
    #pragma unroll
    for(int i=0;i<32;i++){
      int f = t + i*256;             /* 8192 float4s: 64 rows x 128 f4/row */
      int row = f >> 7, c4 = f & 127;
      float4 v = src[(size_t)row*128 + c4];
      float xs[4] = {v.x, v.y, v.z, v.w};
      union { __nv_bfloat16 b[4]; ull u; } hi, lo;
      #pragma unroll
      for(int e=0;e<4;e++){
        __nv_bfloat16 h = __float2bfloat16_rn(xs[e]);
        hi.b[e] = h;
        lo.b[e] = __float2bfloat16_rn(xs[e] - __bfloat162float(h));
      }
      *reinterpret_cast<ull*>(sm + row*A_ROWB + c4*8)          = hi.u;
      *reinterpret_cast<ull*>(sm + SM_ALO + row*A_ROWB + c4*8) = lo.u;
    }
  }

  /* ---- B chunk loader (cp.async, swizzled) ---- */
  auto loadB = [&](int kc, int buf){
    const char* srch = reinterpret_cast<const char*>(g_wbh) + (size_t)kc*B_CHUNK;
    const char* srcl = reinterpret_cast<const char*>(g_wbl) + (size_t)kc*B_CHUNK;
    #pragma unroll
    for(int j=0;j<4;j++){
      int i = t + j*256;             /* 1024 16B lines per buffer */
      int n = i >> 1, kq = i & 1;
      int soff = n*32 + ((kq ^ ((n>>2)&1)) << 4);
      int goff = n*32 + (kq << 4);
      CPA16(sb + SM_BUF(buf,0) + soff, srch + goff);
      CPA16(sb + SM_BUF(buf,1) + soff, srcl + goff);
    }
  };

  loadB(0, 0);
  CPCOMMIT();

  /* per-thread invariant ldmatrix address parts */
  const uint32 a_base = sb + (uint32)((wm*32 + (lane&15))*A_ROWB + (lane>>4)*16);
  const int bnl = (lane&7) + ((lane>>4)&1)*8;
  const uint32 b_base_off = (uint32)((wn*128 + bnl)*32
                          + ((((lane>>3)&1) ^ ((bnl>>2)&1)) << 4));

  float acc[2][16][4];
  #pragma unroll
  for(int mt=0;mt<2;mt++)
    #pragma unroll
    for(int nt=0;nt<16;nt++)
      #pragma unroll
      for(int c=0;c<4;c++) acc[mt][nt][c] = 0.f;

  for(int kc=0; kc<32; kc++){
    const int buf = kc & 1;
    if(kc+1 < 32){ loadB(kc+1, buf^1); CPCOMMIT(); CPWAIT(1); }
    else         { CPWAIT(0); }
    __syncthreads();

    uint32 af[2][4], bf[8][4];
    const uint32 ahi = a_base + kc*32;
    const uint32 alo = ahi + SM_ALO;
    const uint32 bhi = sb + SM_BUF(buf,0) + b_base_off;
    const uint32 blo = sb + SM_BUF(buf,1) + b_base_off;

    /* pass 0: Ah x Bh */
    LDSM4(af[0], ahi);
    LDSM4(af[1], ahi + 16*A_ROWB);
    #pragma unroll
    for(int x=0;x<8;x++) LDSM4(bf[x], bhi + x*512);
    #pragma unroll
    for(int mt=0;mt<2;mt++)
      #pragma unroll
      for(int x=0;x<8;x++){
        MMA16816(acc[mt][2*x],   af[mt], bf[x][0], bf[x][1]);
        MMA16816(acc[mt][2*x+1], af[mt], bf[x][2], bf[x][3]);
      }
    /* pass 1: Al x Bh (B resident) */
    LDSM4(af[0], alo);
    LDSM4(af[1], alo + 16*A_ROWB);
    #pragma unroll
    for(int mt=0;mt<2;mt++)
      #pragma unroll
      for(int x=0;x<8;x++){
        MMA16816(acc[mt][2*x],   af[mt], bf[x][0], bf[x][1]);
        MMA16816(acc[mt][2*x+1], af[mt], bf[x][2], bf[x][3]);
      }
    /* pass 2: Ah x Bl */
    LDSM4(af[0], ahi);
    LDSM4(af[1], ahi + 16*A_ROWB);
    #pragma unroll
    for(int x=0;x<8;x++) LDSM4(bf[x], blo + x*512);
    #pragma unroll
    for(int mt=0;mt<2;mt++)
      #pragma unroll
      for(int x=0;x<8;x++){
        MMA16816(acc[mt][2*x],   af[mt], bf[x][0], bf[x][1]);
        MMA16816(acc[mt][2*x+1], af[mt], bf[x][2], bf[x][3]);
      }
    __syncthreads();
  }

  /* ---- fused epilogue: +y, relu, dot w_time, reduce, softplus, mean ---- */
  const int r = lane >> 2, q = lane & 3;
  float rsum[4] = {0.f,0.f,0.f,0.f};
  #pragma unroll
  for(int mt=0;mt<2;mt++){
    int row0 = wm*32 + mt*16 + r;
    int row1 = row0 + 8;
    int bs0 = (int)((m0 + row0) / NSMP);
    int bs1 = (int)((m0 + row1) / NSMP);
    const float* y0 = g_y + (size_t)bs0*HH;
    const float* y1 = g_y + (size_t)bs1*HH;
    #pragma unroll
    for(int nt=0;nt<16;nt++){
      int col = wn*128 + nt*8 + q*2;
      float w0 = wtime[col], w1 = wtime[col+1];
      float* c = acc[mt][nt];
      rsum[mt*2+0] += fmaxf(c[0]+y0[col],0.f)*w0 + fmaxf(c[1]+y0[col+1],0.f)*w1;
      rsum[mt*2+1] += fmaxf(c[2]+y1[col],0.f)*w0 + fmaxf(c[3]+y1[col+1],0.f)*w1;
    }
  }
  float* rs = reinterpret_cast<float*>(sm);   /* reuse A region: [64][4] */
  #pragma unroll
  for(int s=0;s<4;s++){
    float v = rsum[s];
    v += __shfl_xor_sync(0xffffffffu, v, 1);
    v += __shfl_xor_sync(0xffffffffu, v, 2);
    if(q==0){
      int row = wm*32 + (s>>1)*16 + (s&1)*8 + r;
      rs[row*4 + wn] = v;
    }
  }
  __syncthreads();
  if(t < 64){
    float v = rs[t*4] + rs[t*4+1] + rs[t*4+2] + rs[t*4+3];
    int bsid = (int)((m0 + t) / NSMP);
    atomicAdd(pred + bsid, softplusf(v) * (1.f/NSMP));
  }
}

/* ---------------- launch ---------------- */
extern "C" void kernel_launch(void* const* d_in, const int* in_sizes, int n_in,
                              void* d_out, int out_size){
  const int*   etype  = (const int*)  d_in[0];
  const float* etime  = (const float*)d_in[1];
  const float* noise  = (const float*)d_in[2];
  const float* wt     = (const float*)d_in[3];
  const float* table  = (const float*)d_in[4];
  const float* wsig   = (const float*)d_in[5];
  const float* wgate  = (const float*)d_in[6];
  const float* gamma  = (const float*)d_in[7];
  const float* beta   = (const float*)d_in[8];
  const float* wpred  = (const float*)d_in[9];
  const float* w_in   = (const float*)d_in[10];
  const float* wnoise = (const float*)d_in[11];
  const float* wtime  = (const float*)d_in[12];
  float* out = (float*)d_out;

  cudaFuncSetAttribute(k4_mma, cudaFuncAttributeMaxDynamicSharedMemorySize, K4_SMEM);

  cudaMemsetAsync(out, 0, MM*sizeof(float));          /* pred accum region */
  k0_convB<<<HH*HH/(256*8), 256>>>(wnoise);
  k1_pre<<<MM, 256>>>(etype, etime, wt, table, wsig, wgate);
  k2_agg<<<BB*(SS/8), 256>>>(etime);
  k3_ln <<<MM, 256>>>(gamma, beta, wpred, out + MM);
  k3_y  <<<dim3(MM/64, HH/64), 256>>>(w_in);
  k4_mma<<<RTOT/64, 256, K4_SMEM>>>(noise, wtime, out);
}